// round 12
// baseline (speedup 1.0000x reference)
#include <cuda_runtime.h>
#include <cstdint>

typedef unsigned long long ull;
#define FULL 0xFFFFFFFFu

constexpr int NUM_GROUP  = 512;
constexpr int GROUP_SIZE = 32;
constexpr int TPB        = 512;
constexpr int MAXB       = 64;
constexpr int NBKT       = 4096;

__device__ int g_prog[MAXB];

__global__ void init_prog() {
    if (threadIdx.x < MAXB) g_prog[threadIdx.x] = 0;
}

// ---- packed f32x2 helpers (sm_100+) ----
__device__ __forceinline__ ull pack2(float a, float b) {
    ull r; asm("mov.b64 %0,{%1,%2};" : "=l"(r) : "f"(a), "f"(b)); return r;
}
__device__ __forceinline__ void unpack2(ull v, float& a, float& b) {
    asm("mov.b64 {%0,%1},%2;" : "=f"(a), "=f"(b) : "l"(v));
}
__device__ __forceinline__ ull addx2(ull a, ull b) {
    ull r; asm("add.rn.f32x2 %0,%1,%2;" : "=l"(r) : "l"(a), "l"(b)); return r;
}
__device__ __forceinline__ ull mulx2(ull a, ull b) {
    ull r; asm("mul.rn.f32x2 %0,%1,%2;" : "=l"(r) : "l"(a), "l"(b)); return r;
}
__device__ __forceinline__ ull fma2_(ull a, ull b, ull c) {
    ull r; asm("fma.rn.f32x2 %0,%1,%2,%3;" : "=l"(r) : "l"(a), "l"(b), "l"(c)); return r;
}
__device__ __forceinline__ uint32_t redux_max_u32(uint32_t v) {
    uint32_t r; asm("redux.sync.max.u32 %0, %1, 0xffffffff;" : "=r"(r) : "r"(v)); return r;
}
__device__ __forceinline__ uint32_t redux_min_u32(uint32_t v) {
    uint32_t r; asm("redux.sync.min.u32 %0, %1, 0xffffffff;" : "=r"(r) : "r"(v)); return r;
}
__device__ __forceinline__ void st_release_gpu(int* p, int v) {
    asm volatile("st.release.gpu.global.s32 [%0], %1;" :: "l"(p), "r"(v) : "memory");
}
__device__ __forceinline__ int ld_acquire_gpu(const int* p) {
    int v; asm volatile("ld.acquire.gpu.global.s32 %0, [%1];" : "=r"(v) : "l"(p) : "memory");
    return v;
}
__device__ __forceinline__ float warp_min_f(float v) {
    #pragma unroll
    for (int o = 16; o > 0; o >>= 1) v = fminf(v, __shfl_xor_sync(FULL, v, o));
    return v;
}
__device__ __forceinline__ float warp_max_f(float v) {
    #pragma unroll
    for (int o = 16; o > 0; o >>= 1) v = fmaxf(v, __shfl_xor_sync(FULL, v, o));
    return v;
}

// ============================================================
// Fused kernel, TPB=512:
//   blocks [0, B)        : FPS (x-sorted slabs + exact warp-skip pruning)
//   blocks [B, B + 32*B) : kNN (x-sorted windowed exact top-32), batch-major
// smem layout (both): Bx[N] By[N] Bz[N] (floats), Bid[N] (int), hist[NBKT] (int)
// ============================================================
__global__ __launch_bounds__(TPB)
void fused_kernel(const float* __restrict__ xyz,
                  float* __restrict__ nb,
                  float* __restrict__ centers,
                  int N, int B) {
    extern __shared__ float s[];
    const int tid  = threadIdx.x;
    const int lane = tid & 31;
    const int warp = tid >> 5;

    __shared__ int partial[TPB];

    if (blockIdx.x < (unsigned)B) {
        // ==================== FPS (verbatim r11) ====================
        const int b = blockIdx.x;
        const float* X = xyz + (size_t)b * 3 * N;
        const float* Y = X + N;
        const float* Z = Y + N;
        float* cout = centers + (size_t)b * NUM_GROUP * 3;

        float* Bx = s;
        float* By = s + N;
        float* Bz = s + 2 * N;
        int*   Bid  = (int*)(s + 3 * N);
        int*   hist = (int*)(s + 4 * N);

        __shared__ uint32_t vbuf[2][32];
        __shared__ uint32_t idslot[2];
        __shared__ float    pktc[2][3];
        if (tid < 64) vbuf[tid >> 5][tid & 31] = 0u;
        if (tid < 2)  idslot[tid] = 0xFFFFFFFFu;

        // counting sort by x
        #pragma unroll
        for (int k = 0; k < NBKT / TPB; k++) hist[tid + k * TPB] = 0;
        __syncthreads();
        for (int i = tid; i < N; i += TPB) {
            float x = X[i];
            int bkt = (int)((x + 5.0f) * 409.6f);
            bkt = max(0, min(NBKT - 1, bkt));
            atomicAdd(&hist[bkt], 1);
        }
        __syncthreads();
        int loc[8], mysum = 0;
        #pragma unroll
        for (int k = 0; k < 8; k++) { loc[k] = hist[tid * 8 + k]; mysum += loc[k]; }
        partial[tid] = mysum;
        __syncthreads();
        for (int off = 1; off < TPB; off <<= 1) {
            int v = (tid >= off) ? partial[tid - off] : 0;
            __syncthreads();
            partial[tid] += v;
            __syncthreads();
        }
        {
            int run = partial[tid] - mysum;
            #pragma unroll
            for (int k = 0; k < 8; k++) { int c = loc[k]; hist[tid * 8 + k] = run; run += c; }
        }
        __syncthreads();
        for (int i = tid; i < N; i += TPB) {
            float x = X[i];
            int bkt = (int)((x + 5.0f) * 409.6f);
            bkt = max(0, min(NBKT - 1, bkt));
            int pos = atomicAdd(&hist[bkt], 1);
            Bx[pos]  = x;
            By[pos]  = Y[i];
            Bz[pos]  = Z[i];
            Bid[pos] = i;
        }
        __syncthreads();

        ull  pxp[8], pyp[8], pzp[8];
        uint32_t pp[8];
        float md[16];
        const int base = 512 * warp + 16 * lane;
        float mnx = 1e30f, mxx = -1e30f;
        #pragma unroll
        for (int i = 0; i < 8; i++) {
            int n0 = base + 2 * i;
            float x0 = Bx[n0], x1 = Bx[n0 + 1];
            pxp[i] = pack2(x0, x1);
            pyp[i] = pack2(By[n0], By[n0 + 1]);
            pzp[i] = pack2(Bz[n0], Bz[n0 + 1]);
            pp[i]  = (uint32_t)Bid[n0] | ((uint32_t)Bid[n0 + 1] << 16);
            md[2 * i] = 1e10f; md[2 * i + 1] = 1e10f;
            mnx = fminf(mnx, fminf(x0, x1));
            mxx = fmaxf(mxx, fmaxf(x0, x1));
        }
        const float xlo = warp_min_f(mnx);
        const float xhi = warp_max_f(mxx);

        float cx = X[0], cy = Y[0], cz = Z[0];
        float bvl = 1e10f;
        uint32_t wbits = __float_as_uint(1e10f);
        float wmaxf = 1e10f;
        __syncthreads();

        for (int it = 0; it < NUM_GROUP; it++) {
            const int p = it & 1;
            if (tid == 0) {
                cout[it * 3 + 0] = cx;
                cout[it * 3 + 1] = cy;
                cout[it * 3 + 2] = cz;
                if ((it & 7) == 7) st_release_gpu(&g_prog[b], it - 7);
            }
            if (it == NUM_GROUP - 1) break;

            float L = (cx < xlo) ? (xlo - cx) : ((cx > xhi) ? (cx - xhi) : 0.0f);
            bool skip = (L * L * 0.99999f) >= wmaxf;

            if (!skip) {
                const ull ncx = pack2(-cx, -cx), ncy = pack2(-cy, -cy), ncz = pack2(-cz, -cz);
                float bm0 = -2.0f, bm1 = -2.0f;
                #pragma unroll
                for (int i = 0; i < 8; i++) {
                    ull dx = addx2(pxp[i], ncx);
                    ull dy = addx2(pyp[i], ncy);
                    ull dz = addx2(pzp[i], ncz);
                    ull m  = mulx2(dx, dx);
                    m = fma2_(dy, dy, m);
                    m = fma2_(dz, dz, m);
                    float d0, d1; unpack2(m, d0, d1);
                    float m0 = fminf(md[2 * i],     d0);
                    float m1 = fminf(md[2 * i + 1], d1);
                    md[2 * i]     = m0;
                    md[2 * i + 1] = m1;
                    bm0 = fmaxf(bm0, m0);
                    bm1 = fmaxf(bm1, m1);
                }
                bvl   = fmaxf(bm0, bm1);
                wbits = redux_max_u32(__float_as_uint(bvl));
                wmaxf = __uint_as_float(wbits);
            }
            if (lane == 0) vbuf[p][warp] = wbits;
            __syncthreads();                            // bar A

            if (tid == TPB - 1) idslot[p ^ 1] = 0xFFFFFFFFu;

            uint32_t v2 = vbuf[p][lane];
            uint32_t m2 = redux_max_u32(v2);
            unsigned tiemask = __ballot_sync(FULL, v2 == m2) & 0xFFFFu;
            const bool unique = (__popc(tiemask) == 1);

            if (wbits == m2) {
                uint32_t fb = __float_as_uint(bvl);
                uint32_t q = 0xFFFFFFFFu;
                if (fb == m2) {
                    #pragma unroll
                    for (int j = 0; j < 16; j++) {
                        uint32_t oid = (pp[j >> 1] >> ((j & 1) * 16)) & 0xFFFFu;
                        bool hit = (md[j] == bvl);
                        q = (hit && oid < q) ? oid : q;
                    }
                }
                uint32_t idmin = redux_min_u32(q);

                if (unique) {
                    if (q == idmin && q != 0xFFFFFFFFu) {
                        float wx = 0.f, wy = 0.f, wz = 0.f;
                        #pragma unroll
                        for (int j = 0; j < 16; j++) {
                            uint32_t oid = (pp[j >> 1] >> ((j & 1) * 16)) & 0xFFFFu;
                            bool sel = (md[j] == bvl) && (oid == idmin);
                            float a0, a1; unpack2(pxp[j >> 1], a0, a1);
                            float b0, b1; unpack2(pyp[j >> 1], b0, b1);
                            float c0, c1; unpack2(pzp[j >> 1], c0, c1);
                            wx = sel ? ((j & 1) ? a1 : a0) : wx;
                            wy = sel ? ((j & 1) ? b1 : b0) : wy;
                            wz = sel ? ((j & 1) ? c1 : c0) : wz;
                        }
                        pktc[p][0] = wx; pktc[p][1] = wy; pktc[p][2] = wz;
                    }
                } else {
                    if (lane == 0) atomicMin(&idslot[p], idmin);
                }
            }
            __syncthreads();                            // bar B

            if (!unique) {
                if (wbits == m2) {
                    uint32_t fb = __float_as_uint(bvl);
                    uint32_t gid = idslot[p];
                    if (fb == m2) {
                        float wx = 0.f, wy = 0.f, wz = 0.f;
                        bool own = false;
                        #pragma unroll
                        for (int j = 0; j < 16; j++) {
                            uint32_t oid = (pp[j >> 1] >> ((j & 1) * 16)) & 0xFFFFu;
                            bool sel = (md[j] == bvl) && (oid == gid);
                            float a0, a1; unpack2(pxp[j >> 1], a0, a1);
                            float b0, b1; unpack2(pyp[j >> 1], b0, b1);
                            float c0, c1; unpack2(pzp[j >> 1], c0, c1);
                            wx = sel ? ((j & 1) ? a1 : a0) : wx;
                            wy = sel ? ((j & 1) ? b1 : b0) : wy;
                            wz = sel ? ((j & 1) ? c1 : c0) : wz;
                            own |= sel;
                        }
                        if (own) { pktc[p][0] = wx; pktc[p][1] = wy; pktc[p][2] = wz; }
                    }
                }
                __syncthreads();                        // bar C (rare)
            }

            cx = pktc[p][0];
            cy = pktc[p][1];
            cz = pktc[p][2];
        }
        if (tid == 0) st_release_gpu(&g_prog[b], NUM_GROUP);
    } else {
        // ==================== kNN: x-sorted windowed exact top-32 ====================
        float* sx = s;
        float* sy = s + N;
        float* sz = s + 2 * N;
        int*   soid = (int*)(s + 3 * N);
        int*   hist = (int*)(s + 4 * N);

        const int kb    = blockIdx.x - B;
        const int b     = kb % B;                   // batch-major
        const int chunk = kb / B;
        const int g     = chunk * 16 + warp;

        const float* X = xyz + (size_t)b * 3 * N;
        const float* Y = X + N;
        const float* Z = Y + N;

        // ---- counting sort by x (same as FPS) ----
        #pragma unroll
        for (int k = 0; k < NBKT / TPB; k++) hist[tid + k * TPB] = 0;
        __syncthreads();
        for (int i = tid; i < N; i += TPB) {
            float x = X[i];
            int bkt = (int)((x + 5.0f) * 409.6f);
            bkt = max(0, min(NBKT - 1, bkt));
            atomicAdd(&hist[bkt], 1);
        }
        __syncthreads();
        int loc[8], mysum = 0;
        #pragma unroll
        for (int k = 0; k < 8; k++) { loc[k] = hist[tid * 8 + k]; mysum += loc[k]; }
        partial[tid] = mysum;
        __syncthreads();
        for (int off = 1; off < TPB; off <<= 1) {
            int v = (tid >= off) ? partial[tid - off] : 0;
            __syncthreads();
            partial[tid] += v;
            __syncthreads();
        }
        {
            int run = partial[tid] - mysum;
            #pragma unroll
            for (int k = 0; k < 8; k++) { int c = loc[k]; hist[tid * 8 + k] = run; run += c; }
        }
        __syncthreads();
        for (int i = tid; i < N; i += TPB) {
            float x = X[i];
            int bkt = (int)((x + 5.0f) * 409.6f);
            bkt = max(0, min(NBKT - 1, bkt));
            int pos = atomicAdd(&hist[bkt], 1);
            sx[pos]   = x;
            sy[pos]   = Y[i];
            sz[pos]   = Z[i];
            soid[pos] = i;
        }
        __syncthreads();
        // hist[b] now holds END offset of bucket b.

        // ---- wait for this group's center ----
        if (lane == 0) {
            while (ld_acquire_gpu(&g_prog[b]) < g + 1) __nanosleep(512);
        }
        __syncwarp();

        const float* c = centers + ((size_t)b * NUM_GROUP + g) * 3;
        const float cx = __ldcg(&c[0]), cy = __ldcg(&c[1]), cz = __ldcg(&c[2]);

        // ---- start position from bucket histogram ----
        int cb = (int)((cx + 5.0f) * 409.6f);
        cb = max(0, min(NBKT - 1, cb));
        int start = (cb == 0) ? 0 : hist[cb - 1];
        int pos0 = min(max(start - 16, 0), N - 32);

        // ---- init with 32 points around start, bitonic sort ascending ----
        ull key;
        {
            int sp = pos0 + lane;
            float dx = sx[sp] - cx, dy = sy[sp] - cy, dz = sz[sp] - cz;
            float d2 = fmaf(dz, dz, fmaf(dy, dy, dx * dx));
            key = ((ull)__float_as_uint(d2) << 32) | (uint32_t)soid[sp];
        }
        #pragma unroll
        for (int k2 = 2; k2 <= 32; k2 <<= 1) {
            #pragma unroll
            for (int j = k2 >> 1; j > 0; j >>= 1) {
                ull partner = __shfl_xor_sync(FULL, key, j);
                bool lower  = (lane & j) == 0;
                bool asc    = (lane & k2) == 0;
                ull mn = (key < partner) ? key : partner;
                ull mx = (key < partner) ? partner : key;
                key = (lower == asc) ? mn : mx;
            }
        }
        ull kmax   = __shfl_sync(FULL, key, 31);
        float kthd = __uint_as_float((uint32_t)(kmax >> 32));

        // ---- outward expansion with exact pruning ----
        const float BKTW = 0.0025f;                // bucket width upper bound
        int rb = pos0 + 32;
        int lb = pos0 - 32;
        bool rdone = (rb >= N);
        bool ldone = (lb <= -32);

        while (!(rdone && ldone)) {
            float rEff, lEff;
            if (rdone) rEff = 3.0e38f;
            else {
                float bx = sx[rb];                 // uniform broadcast LDS
                rEff = (fabsf(bx) > 4.99f) ? 0.0f : fmaxf(bx - cx - BKTW, 0.0f);
            }
            if (ldone) lEff = 3.0e38f;
            else {
                float bx = sx[lb + 31];
                lEff = (fabsf(bx) > 4.99f) ? 0.0f : fmaxf(cx - bx - BKTW, 0.0f);
            }
            float m = fminf(rEff, lEff);
            if (m * m * 0.999f > kthd) break;       // exact-conservative prune

            bool right = (rEff <= lEff);
            int base = right ? rb : lb;

            int idx  = base + lane;
            int cidx = min(max(idx, 0), N - 1);
            float dx = sx[cidx] - cx, dy = sy[cidx] - cy, dz = sz[cidx] - cz;
            float d2 = fmaf(dz, dz, fmaf(dy, dy, dx * dx));
            bool valid = (idx >= 0) && (idx < N);
            bool ok = valid && (d2 <= kthd);        // <= : keeps equal-d2 smaller-id candidates
            ull nk = ((ull)__float_as_uint(d2) << 32) | (uint32_t)soid[cidx];

            unsigned mask = __ballot_sync(FULL, ok);
            while (mask) {
                int src = __ffs(mask) - 1;
                mask &= mask - 1;
                ull cand = __shfl_sync(FULL, nk, src);
                if (cand >= kmax) continue;         // exact decision
                int pos = __popc(__ballot_sync(FULL, key < cand));
                ull up  = __shfl_up_sync(FULL, key, 1);
                if (lane == pos)      key = cand;
                else if (lane > pos)  key = up;
                kmax = __shfl_sync(FULL, key, 31);
                kthd = __uint_as_float((uint32_t)(kmax >> 32));
            }

            if (right) { rb += 32; rdone = (rb >= N); }
            else       { lb -= 32; ldone = (lb <= -32); }
        }

        // ---- emit: gather coords by original id, neighborhood = point - center ----
        uint32_t oidw = (uint32_t)key;
        float px = __ldg(X + oidw);
        float py = __ldg(Y + oidw);
        float pz = __ldg(Z + oidw);
        size_t o = (((size_t)b * NUM_GROUP + g) * GROUP_SIZE + lane) * 3;
        nb[o + 0] = px - cx;
        nb[o + 1] = py - cy;
        nb[o + 2] = pz - cz;
    }
}

// ============================================================
extern "C" void kernel_launch(void* const* d_in, const int* in_sizes, int n_in,
                              void* d_out, int out_size) {
    const float* xyz = (const float*)d_in[0];
    float* out = (float*)d_out;

    const int B = out_size / (NUM_GROUP * (GROUP_SIZE + 1) * 3);
    const int N = in_sizes[0] / (3 * B);

    float* nb      = out;
    float* centers = out + (size_t)B * NUM_GROUP * GROUP_SIZE * 3;

    const int knnBlocks = B * (NUM_GROUP / 16);
    size_t smem = (size_t)(4 * N + NBKT) * sizeof(float);   // Bx,By,Bz,Bid/soid + hist
    if (smem < 120 * 1024) smem = 120 * 1024;               // force 1 block/SM

    init_prog<<<1, MAXB>>>();

    cudaFuncSetAttribute(fused_kernel, cudaFuncAttributeMaxDynamicSharedMemorySize, (int)smem);
    fused_kernel<<<B + knnBlocks, TPB, smem>>>(xyz, nb, centers, N, B);
}

// round 13
// speedup vs baseline: 1.3422x; 1.3422x over previous
#include <cuda_runtime.h>
#include <cstdint>

typedef unsigned long long ull;
#define FULL 0xFFFFFFFFu

constexpr int NUM_GROUP  = 512;
constexpr int GROUP_SIZE = 32;
constexpr int TPB        = 512;
constexpr int MAXB       = 64;
constexpr int NBKT       = 4096;

__device__ int g_prog[MAXB];

__global__ void init_prog() {
    if (threadIdx.x < MAXB) g_prog[threadIdx.x] = 0;
}

// ---- packed f32x2 helpers (sm_100+) ----
__device__ __forceinline__ ull pack2(float a, float b) {
    ull r; asm("mov.b64 %0,{%1,%2};" : "=l"(r) : "f"(a), "f"(b)); return r;
}
__device__ __forceinline__ void unpack2(ull v, float& a, float& b) {
    asm("mov.b64 {%0,%1},%2;" : "=f"(a), "=f"(b) : "l"(v));
}
__device__ __forceinline__ ull addx2(ull a, ull b) {
    ull r; asm("add.rn.f32x2 %0,%1,%2;" : "=l"(r) : "l"(a), "l"(b)); return r;
}
__device__ __forceinline__ ull mulx2(ull a, ull b) {
    ull r; asm("mul.rn.f32x2 %0,%1,%2;" : "=l"(r) : "l"(a), "l"(b)); return r;
}
__device__ __forceinline__ ull fma2_(ull a, ull b, ull c) {
    ull r; asm("fma.rn.f32x2 %0,%1,%2,%3;" : "=l"(r) : "l"(a), "l"(b), "l"(c)); return r;
}
__device__ __forceinline__ uint32_t redux_max_u32(uint32_t v) {
    uint32_t r; asm("redux.sync.max.u32 %0, %1, 0xffffffff;" : "=r"(r) : "r"(v)); return r;
}
__device__ __forceinline__ uint32_t redux_min_u32(uint32_t v) {
    uint32_t r; asm("redux.sync.min.u32 %0, %1, 0xffffffff;" : "=r"(r) : "r"(v)); return r;
}
__device__ __forceinline__ void st_release_gpu(int* p, int v) {
    asm volatile("st.release.gpu.global.s32 [%0], %1;" :: "l"(p), "r"(v) : "memory");
}
__device__ __forceinline__ int ld_acquire_gpu(const int* p) {
    int v; asm volatile("ld.acquire.gpu.global.s32 %0, [%1];" : "=r"(v) : "l"(p) : "memory");
    return v;
}
__device__ __forceinline__ float warp_min_f(float v) {
    #pragma unroll
    for (int o = 16; o > 0; o >>= 1) v = fminf(v, __shfl_xor_sync(FULL, v, o));
    return v;
}
__device__ __forceinline__ float warp_max_f(float v) {
    #pragma unroll
    for (int o = 16; o > 0; o >>= 1) v = fmaxf(v, __shfl_xor_sync(FULL, v, o));
    return v;
}

// ============================================================
// Fused kernel, TPB=512:
//   blocks [0, B)        : FPS (x-sorted slabs + exact warp-skip pruning)
//   blocks [B, B + 32*B) : kNN (r10 streaming, proven), batch-major
// FPS smem: Bx[N] By[N] Bz[N] floats, Bid[N] int, hist[NBKT] int
// ============================================================
__global__ __launch_bounds__(TPB)
void fused_kernel(const float* __restrict__ xyz,
                  float* __restrict__ nb,
                  float* __restrict__ centers,
                  int N, int B) {
    extern __shared__ float s[];
    const int tid  = threadIdx.x;
    const int lane = tid & 31;
    const int warp = tid >> 5;

    __shared__ int partial[TPB];

    if (blockIdx.x < (unsigned)B) {
        // ==================== FPS ====================
        const int b = blockIdx.x;
        const float* X = xyz + (size_t)b * 3 * N;
        const float* Y = X + N;
        const float* Z = Y + N;
        float* cout = centers + (size_t)b * NUM_GROUP * 3;

        float* Bx = s;
        float* By = s + N;
        float* Bz = s + 2 * N;
        int*   Bid  = (int*)(s + 3 * N);
        int*   hist = (int*)(s + 4 * N);

        __shared__ uint32_t vbuf[2][32];     // per-warp value table (lanes 16..31 stay 0)
        __shared__ uint32_t posslot[2];      // winner's SORTED position (plain STS)
        __shared__ uint32_t oidslot[2];      // rare cross-warp tie: original-id atomicMin
        if (tid < 64) vbuf[tid >> 5][tid & 31] = 0u;
        if (tid < 2)  oidslot[tid] = 0xFFFFFFFFu;

        // ---- counting sort by x (4096 buckets over [-5,5]) ----
        #pragma unroll
        for (int k = 0; k < NBKT / TPB; k++) hist[tid + k * TPB] = 0;
        __syncthreads();
        for (int i = tid; i < N; i += TPB) {
            float x = X[i];
            int bkt = (int)((x + 5.0f) * 409.6f);
            bkt = max(0, min(NBKT - 1, bkt));
            atomicAdd(&hist[bkt], 1);
        }
        __syncthreads();
        int loc[8], mysum = 0;
        #pragma unroll
        for (int k = 0; k < 8; k++) { loc[k] = hist[tid * 8 + k]; mysum += loc[k]; }
        partial[tid] = mysum;
        __syncthreads();
        for (int off = 1; off < TPB; off <<= 1) {
            int v = (tid >= off) ? partial[tid - off] : 0;
            __syncthreads();
            partial[tid] += v;
            __syncthreads();
        }
        {
            int run = partial[tid] - mysum;
            #pragma unroll
            for (int k = 0; k < 8; k++) { int c = loc[k]; hist[tid * 8 + k] = run; run += c; }
        }
        __syncthreads();
        for (int i = tid; i < N; i += TPB) {
            float x = X[i];
            int bkt = (int)((x + 5.0f) * 409.6f);
            bkt = max(0, min(NBKT - 1, bkt));
            int pos = atomicAdd(&hist[bkt], 1);
            Bx[pos]  = x;
            By[pos]  = Y[i];
            Bz[pos]  = Z[i];
            Bid[pos] = i;
        }
        __syncthreads();

        // ---- 16 contiguous sorted points per thread ----
        ull  pxp[8], pyp[8], pzp[8];
        uint32_t pp[8];                      // 2 original ids per reg (16-bit each)
        float md[16];
        const int base = 512 * warp + 16 * lane;
        float mnx = 1e30f, mxx = -1e30f;
        #pragma unroll
        for (int i = 0; i < 8; i++) {
            int n0 = base + 2 * i;
            float x0 = Bx[n0], x1 = Bx[n0 + 1];
            pxp[i] = pack2(x0, x1);
            pyp[i] = pack2(By[n0], By[n0 + 1]);
            pzp[i] = pack2(Bz[n0], Bz[n0 + 1]);
            pp[i]  = (uint32_t)Bid[n0] | ((uint32_t)Bid[n0 + 1] << 16);
            md[2 * i] = 1e10f; md[2 * i + 1] = 1e10f;
            mnx = fminf(mnx, fminf(x0, x1));
            mxx = fmaxf(mxx, fmaxf(x0, x1));
        }
        const float xlo = warp_min_f(mnx);   // exact slab bounds (warp-uniform)
        const float xhi = warp_max_f(mxx);

        float cx = X[0], cy = Y[0], cz = Z[0];
        float bvl = 1e10f;
        uint32_t wbits = __float_as_uint(1e10f);
        float wmaxf = 1e10f;
        __syncthreads();

        for (int it = 0; it < NUM_GROUP; it++) {
            const int p = it & 1;
            if (tid == 0) {
                // release FIRST: orders only >=1-iteration-old stores -> fence ~free
                if ((it & 7) == 0 && it > 0) st_release_gpu(&g_prog[b], it);
                cout[it * 3 + 0] = cx;
                cout[it * 3 + 1] = cy;
                cout[it * 3 + 2] = cz;
            }
            if (it == NUM_GROUP - 1) break;

            // exact slab pruning (proven in r11: skip leaves all md bit-unchanged)
            float L = (cx < xlo) ? (xlo - cx) : ((cx > xhi) ? (cx - xhi) : 0.0f);
            bool skip = (L * L * 0.99999f) >= wmaxf;   // warp-uniform

            if (!skip) {
                const ull ncx = pack2(-cx, -cx), ncy = pack2(-cy, -cy), ncz = pack2(-cz, -cz);
                float bm0 = -2.0f, bm1 = -2.0f;
                #pragma unroll
                for (int i = 0; i < 8; i++) {
                    ull dx = addx2(pxp[i], ncx);
                    ull dy = addx2(pyp[i], ncy);
                    ull dz = addx2(pzp[i], ncz);
                    ull m  = mulx2(dx, dx);
                    m = fma2_(dy, dy, m);
                    m = fma2_(dz, dz, m);    // == fmaf(dz,dz,fmaf(dy,dy,dx*dx)) per lane
                    float d0, d1; unpack2(m, d0, d1);
                    float m0 = fminf(md[2 * i],     d0);
                    float m1 = fminf(md[2 * i + 1], d1);
                    md[2 * i]     = m0;
                    md[2 * i + 1] = m1;
                    bm0 = fmaxf(bm0, m0);
                    bm1 = fmaxf(bm1, m1);
                }
                bvl   = fmaxf(bm0, bm1);
                wbits = redux_max_u32(__float_as_uint(bvl));   // md>=0 -> bits monotone
                wmaxf = __uint_as_float(wbits);
            }
            if (lane == 0) vbuf[p][warp] = wbits;
            __syncthreads();                            // bar A

            if (tid == TPB - 1) oidslot[p ^ 1] = 0xFFFFFFFFu;  // reset for it+1 tie path

            uint32_t v2 = vbuf[p][lane];
            uint32_t m2 = redux_max_u32(v2);            // block max (uniform)
            unsigned tiemask = __ballot_sync(FULL, v2 == m2) & 0xFFFFu;
            const bool unique = (__popc(tiemask) == 1);

            // winner warp(s): per-lane static scan -> (min original id, its slot)
            uint32_t oq = 0xFFFFFFFFu;
            int jmin = 0;
            if (wbits == m2) {
                if (__float_as_uint(bvl) == m2) {
                    #pragma unroll
                    for (int j = 0; j < 16; j++) {
                        uint32_t oid = (pp[j >> 1] >> ((j & 1) * 16)) & 0xFFFFu;
                        bool hit = (md[j] == bvl) && (oid < oq);
                        oq   = hit ? oid : oq;
                        jmin = hit ? j   : jmin;
                    }
                }
                uint32_t idmin = redux_min_u32(oq);
                if (unique) {
                    if (oq == idmin && oq != 0xFFFFFFFFu)
                        posslot[p] = (uint32_t)(base + jmin);   // exact: min oid's position
                } else {
                    if (lane == 0) atomicMin(&oidslot[p], idmin);
                }
            }
            __syncthreads();                            // bar B (drains winner STS)

            if (!unique) {                               // rare, block-uniform
                if (wbits == m2 && oq != 0xFFFFFFFFu && oq == oidslot[p])
                    posslot[p] = (uint32_t)(base + jmin);
                __syncthreads();                        // bar C (rare)
            }

            int pos = (int)posslot[p];                  // LDS
            cx = Bx[pos]; cy = By[pos]; cz = Bz[pos];   // parallel broadcast LDS
        }
        if (tid == 0) st_release_gpu(&g_prog[b], NUM_GROUP);
    } else {
        // ==================== kNN top-32 (r10 streaming, batch-major) ====================
        float* sx = s;
        float* sy = s + N;
        float* sz = s + 2 * N;

        const int kb    = blockIdx.x - B;
        const int b     = kb % B;
        const int chunk = kb / B;
        const int g     = chunk * 16 + warp;

        const float* X = xyz + (size_t)b * 3 * N;
        const float4* X4 = (const float4*)X;
        float4* sx4 = (float4*)sx;
        float4* sy4 = (float4*)sy;
        float4* sz4 = (float4*)sz;
        const int N4 = N >> 2;
        for (int n = tid; n < N4; n += TPB) {
            sx4[n] = X4[n];
            sy4[n] = X4[N4 + n];
            sz4[n] = X4[2 * N4 + n];
        }
        __syncthreads();

        if (lane == 0) {
            while (ld_acquire_gpu(&g_prog[b]) < g + 1) __nanosleep(512);
        }
        __syncwarp();

        const float* c = centers + ((size_t)b * NUM_GROUP + g) * 3;
        const float cx = __ldcg(&c[0]), cy = __ldcg(&c[1]), cz = __ldcg(&c[2]);

        // init with first 32 points, bitonic sort ascending u64 keys
        ull key;
        {
            float dx = sx[lane] - cx, dy = sy[lane] - cy, dz = sz[lane] - cz;
            float d2 = fmaf(dz, dz, fmaf(dy, dy, dx * dx));
            key = ((ull)__float_as_uint(d2) << 32) | (uint32_t)lane;
        }
        #pragma unroll
        for (int k2 = 2; k2 <= 32; k2 <<= 1) {
            #pragma unroll
            for (int j = k2 >> 1; j > 0; j >>= 1) {
                ull partner = __shfl_xor_sync(FULL, key, j);
                bool lower  = (lane & j) == 0;
                bool asc    = (lane & k2) == 0;
                ull mn = (key < partner) ? key : partner;
                ull mx = (key < partner) ? partner : key;
                key = (lower == asc) ? mn : mx;
            }
        }
        ull kmax = __shfl_sync(FULL, key, 31);

        // scalar step for points [32, 64)
        {
            int idx = 32 + lane;
            float dx = sx[idx] - cx, dy = sy[idx] - cy, dz = sz[idx] - cz;
            float d2 = fmaf(dz, dz, fmaf(dy, dy, dx * dx));
            ull nk = ((ull)__float_as_uint(d2) << 32) | (uint32_t)idx;
            unsigned mask = __ballot_sync(FULL, nk < kmax);
            while (mask) {
                int src = __ffs(mask) - 1;
                mask &= mask - 1;
                ull cand = __shfl_sync(FULL, nk, src);
                if (cand >= kmax) continue;
                int pos = __popc(__ballot_sync(FULL, key < cand));
                ull up  = __shfl_up_sync(FULL, key, 1);
                if (lane == pos)      key = cand;
                else if (lane > pos)  key = up;
                kmax = __shfl_sync(FULL, key, 31);
            }
        }

        // packed stream: 64 candidates per step
        const float2* sx2 = (const float2*)sx;
        const float2* sy2 = (const float2*)sy;
        const float2* sz2 = (const float2*)sz;
        const ull ncx = pack2(-cx, -cx), ncy = pack2(-cy, -cy), ncz = pack2(-cz, -cz);

        for (int base2 = 64; base2 < N; base2 += 64) {
            int h = (base2 >> 1) + lane;
            float2 xx = sx2[h], yy = sy2[h], zz = sz2[h];
            ull dx = addx2(pack2(xx.x, xx.y), ncx);
            ull dy = addx2(pack2(yy.x, yy.y), ncy);
            ull dz = addx2(pack2(zz.x, zz.y), ncz);
            ull m  = mulx2(dx, dx);
            m = fma2_(dy, dy, m);
            m = fma2_(dz, dz, m);
            float d0, d1; unpack2(m, d0, d1);
            int i0 = base2 + 2 * lane;
            ull k0 = ((ull)__float_as_uint(d0) << 32) | (uint32_t)i0;
            ull k1 = ((ull)__float_as_uint(d1) << 32) | (uint32_t)(i0 + 1);

            unsigned m0 = __ballot_sync(FULL, k0 < kmax);
            unsigned m1 = __ballot_sync(FULL, k1 < kmax);
            while (m0) {
                int src = __ffs(m0) - 1;
                m0 &= m0 - 1;
                ull cand = __shfl_sync(FULL, k0, src);
                if (cand >= kmax) continue;
                int pos = __popc(__ballot_sync(FULL, key < cand));
                ull up  = __shfl_up_sync(FULL, key, 1);
                if (lane == pos)      key = cand;
                else if (lane > pos)  key = up;
                kmax = __shfl_sync(FULL, key, 31);
            }
            while (m1) {
                int src = __ffs(m1) - 1;
                m1 &= m1 - 1;
                ull cand = __shfl_sync(FULL, k1, src);
                if (cand >= kmax) continue;
                int pos = __popc(__ballot_sync(FULL, key < cand));
                ull up  = __shfl_up_sync(FULL, key, 1);
                if (lane == pos)      key = cand;
                else if (lane > pos)  key = up;
                kmax = __shfl_sync(FULL, key, 31);
            }
        }

        // emit: neighborhood = point - center (lane-sorted ascending = top_k order)
        int idx = (int)(uint32_t)key;
        float ox = sx[idx] - cx, oy = sy[idx] - cy, oz = sz[idx] - cz;
        size_t o = (((size_t)b * NUM_GROUP + g) * GROUP_SIZE + lane) * 3;
        nb[o + 0] = ox;
        nb[o + 1] = oy;
        nb[o + 2] = oz;
    }
}

// ============================================================
extern "C" void kernel_launch(void* const* d_in, const int* in_sizes, int n_in,
                              void* d_out, int out_size) {
    const float* xyz = (const float*)d_in[0];
    float* out = (float*)d_out;

    const int B = out_size / (NUM_GROUP * (GROUP_SIZE + 1) * 3);
    const int N = in_sizes[0] / (3 * B);

    float* nb      = out;
    float* centers = out + (size_t)B * NUM_GROUP * GROUP_SIZE * 3;

    const int knnBlocks = B * (NUM_GROUP / 16);
    size_t smem = (size_t)(4 * N + NBKT) * sizeof(float);   // Bx,By,Bz,Bid + hist
    if (smem < 120 * 1024) smem = 120 * 1024;               // force 1 block/SM

    init_prog<<<1, MAXB>>>();

    cudaFuncSetAttribute(fused_kernel, cudaFuncAttributeMaxDynamicSharedMemorySize, (int)smem);
    fused_kernel<<<B + knnBlocks, TPB, smem>>>(xyz, nb, centers, N, B);
}

// round 14
// speedup vs baseline: 1.7238x; 1.2843x over previous
#include <cuda_runtime.h>
#include <cstdint>

typedef unsigned long long ull;
#define FULL 0xFFFFFFFFu

constexpr int NUM_GROUP  = 512;
constexpr int GROUP_SIZE = 32;
constexpr int TPB        = 512;
constexpr int MAXB       = 64;
constexpr int NBKT       = 4096;

__device__ int g_prog[MAXB];

__global__ void init_prog() {
    if (threadIdx.x < MAXB) g_prog[threadIdx.x] = 0;
}

// ---- packed f32x2 helpers (sm_100+) ----
__device__ __forceinline__ ull pack2(float a, float b) {
    ull r; asm("mov.b64 %0,{%1,%2};" : "=l"(r) : "f"(a), "f"(b)); return r;
}
__device__ __forceinline__ void unpack2(ull v, float& a, float& b) {
    asm("mov.b64 {%0,%1},%2;" : "=f"(a), "=f"(b) : "l"(v));
}
__device__ __forceinline__ ull addx2(ull a, ull b) {
    ull r; asm("add.rn.f32x2 %0,%1,%2;" : "=l"(r) : "l"(a), "l"(b)); return r;
}
__device__ __forceinline__ ull mulx2(ull a, ull b) {
    ull r; asm("mul.rn.f32x2 %0,%1,%2;" : "=l"(r) : "l"(a), "l"(b)); return r;
}
__device__ __forceinline__ ull fma2_(ull a, ull b, ull c) {
    ull r; asm("fma.rn.f32x2 %0,%1,%2,%3;" : "=l"(r) : "l"(a), "l"(b), "l"(c)); return r;
}
__device__ __forceinline__ uint32_t redux_max_u32(uint32_t v) {
    uint32_t r; asm("redux.sync.max.u32 %0, %1, 0xffffffff;" : "=r"(r) : "r"(v)); return r;
}
__device__ __forceinline__ uint32_t redux_min_u32(uint32_t v) {
    uint32_t r; asm("redux.sync.min.u32 %0, %1, 0xffffffff;" : "=r"(r) : "r"(v)); return r;
}
__device__ __forceinline__ void st_release_gpu(int* p, int v) {
    asm volatile("st.release.gpu.global.s32 [%0], %1;" :: "l"(p), "r"(v) : "memory");
}
__device__ __forceinline__ int ld_acquire_gpu(const int* p) {
    int v; asm volatile("ld.acquire.gpu.global.s32 %0, [%1];" : "=r"(v) : "l"(p) : "memory");
    return v;
}
__device__ __forceinline__ float warp_min_f(float v) {
    #pragma unroll
    for (int o = 16; o > 0; o >>= 1) v = fminf(v, __shfl_xor_sync(FULL, v, o));
    return v;
}
__device__ __forceinline__ float warp_max_f(float v) {
    #pragma unroll
    for (int o = 16; o > 0; o >>= 1) v = fmaxf(v, __shfl_xor_sync(FULL, v, o));
    return v;
}

// ============================================================
// Fused kernel, TPB=512:
//   blocks [0, B)        : FPS — single barrier/iter, pre-resolved warp packets
//   blocks [B, B + 32*B) : kNN (r10 streaming, proven), batch-major
// FPS smem: Bx[N] By[N] Bz[N] floats, Bid[N] int, hist[NBKT] int
// ============================================================
__global__ __launch_bounds__(TPB)
void fused_kernel(const float* __restrict__ xyz,
                  float* __restrict__ nb,
                  float* __restrict__ centers,
                  int N, int B) {
    extern __shared__ float s[];
    const int tid  = threadIdx.x;
    const int lane = tid & 31;
    const int warp = tid >> 5;

    __shared__ int partial[TPB];

    if (blockIdx.x < (unsigned)B) {
        // ==================== FPS ====================
        const int b = blockIdx.x;
        const float* X = xyz + (size_t)b * 3 * N;
        const float* Y = X + N;
        const float* Z = Y + N;
        float* cout = centers + (size_t)b * NUM_GROUP * 3;

        float* Bx = s;
        float* By = s + N;
        float* Bz = s + 2 * N;
        int*   Bid  = (int*)(s + 3 * N);
        int*   hist = (int*)(s + 4 * N);

        __shared__ uint32_t vbuf[2][32];   // per-warp value bits (lanes 16..31 stay 0)
        __shared__ uint32_t pbuf[2][32];   // per-warp packed (oid<<16 | pos)
        if (tid < 64) {
            vbuf[tid >> 5][tid & 31] = 0u;
            pbuf[tid >> 5][tid & 31] = 0xFFFFFFFFu;
        }

        // ---- counting sort by x (4096 buckets over [-5,5]) ----
        #pragma unroll
        for (int k = 0; k < NBKT / TPB; k++) hist[tid + k * TPB] = 0;
        __syncthreads();
        for (int i = tid; i < N; i += TPB) {
            float x = X[i];
            int bkt = (int)((x + 5.0f) * 409.6f);
            bkt = max(0, min(NBKT - 1, bkt));
            atomicAdd(&hist[bkt], 1);
        }
        __syncthreads();
        int loc[8], mysum = 0;
        #pragma unroll
        for (int k = 0; k < 8; k++) { loc[k] = hist[tid * 8 + k]; mysum += loc[k]; }
        partial[tid] = mysum;
        __syncthreads();
        for (int off = 1; off < TPB; off <<= 1) {
            int v = (tid >= off) ? partial[tid - off] : 0;
            __syncthreads();
            partial[tid] += v;
            __syncthreads();
        }
        {
            int run = partial[tid] - mysum;
            #pragma unroll
            for (int k = 0; k < 8; k++) { int c = loc[k]; hist[tid * 8 + k] = run; run += c; }
        }
        __syncthreads();
        for (int i = tid; i < N; i += TPB) {
            float x = X[i];
            int bkt = (int)((x + 5.0f) * 409.6f);
            bkt = max(0, min(NBKT - 1, bkt));
            int pos = atomicAdd(&hist[bkt], 1);
            Bx[pos]  = x;
            By[pos]  = Y[i];
            Bz[pos]  = Z[i];
            Bid[pos] = i;
        }
        __syncthreads();

        // ---- 16 contiguous sorted points per thread ----
        ull  pxp[8], pyp[8], pzp[8];
        uint32_t oidpos[16];               // (original_id << 16) | sorted_pos, per slot
        float md[16];
        const int base = 512 * warp + 16 * lane;
        float mnx = 1e30f, mxx = -1e30f;
        #pragma unroll
        for (int i = 0; i < 8; i++) {
            int n0 = base + 2 * i;
            float x0 = Bx[n0], x1 = Bx[n0 + 1];
            pxp[i] = pack2(x0, x1);
            pyp[i] = pack2(By[n0], By[n0 + 1]);
            pzp[i] = pack2(Bz[n0], Bz[n0 + 1]);
            oidpos[2 * i]     = ((uint32_t)Bid[n0]     << 16) | (uint32_t)n0;
            oidpos[2 * i + 1] = ((uint32_t)Bid[n0 + 1] << 16) | (uint32_t)(n0 + 1);
            md[2 * i] = 1e10f; md[2 * i + 1] = 1e10f;
            mnx = fminf(mnx, fminf(x0, x1));
            mxx = fmaxf(mxx, fmaxf(x0, x1));
        }
        const float xlo = warp_min_f(mnx);   // exact slab bounds (warp-uniform)
        const float xhi = warp_max_f(mxx);

        float cx = X[0], cy = Y[0], cz = Z[0];
        float bvl = 1e10f;
        uint32_t wbits = __float_as_uint(1e10f);
        float    wmaxf = 1e10f;
        uint32_t q32w  = 0xFFFFFFFFu;        // cached warp packet (for skipped iters)
        __syncthreads();

        for (int it = 0; it < NUM_GROUP; it++) {
            const int p = it & 1;
            if (tid == 0) {
                if ((it & 7) == 0 && it > 0) st_release_gpu(&g_prog[b], it);
                cout[it * 3 + 0] = cx;
                cout[it * 3 + 1] = cy;
                cout[it * 3 + 2] = cz;
            }
            if (it == NUM_GROUP - 1) break;

            // exact slab pruning: skip leaves all md (hence packet) bit-unchanged
            float L = (cx < xlo) ? (xlo - cx) : ((cx > xhi) ? (cx - xhi) : 0.0f);
            bool skip = (L * L * 0.99999f) >= wmaxf;   // warp-uniform

            if (!skip) {
                const ull ncx = pack2(-cx, -cx), ncy = pack2(-cy, -cy), ncz = pack2(-cz, -cz);
                float bm0 = -2.0f, bm1 = -2.0f;
                #pragma unroll
                for (int i = 0; i < 8; i++) {
                    ull dx = addx2(pxp[i], ncx);
                    ull dy = addx2(pyp[i], ncy);
                    ull dz = addx2(pzp[i], ncz);
                    ull m  = mulx2(dx, dx);
                    m = fma2_(dy, dy, m);
                    m = fma2_(dz, dz, m);    // == fmaf(dz,dz,fmaf(dy,dy,dx*dx)) per lane
                    float d0, d1; unpack2(m, d0, d1);
                    float m0 = fminf(md[2 * i],     d0);
                    float m1 = fminf(md[2 * i + 1], d1);
                    md[2 * i]     = m0;
                    md[2 * i + 1] = m1;
                    bm0 = fmaxf(bm0, m0);
                    bm1 = fmaxf(bm1, m1);
                }
                bvl   = fmaxf(bm0, bm1);
                uint32_t fb = (bvl >= 0.0f) ? __float_as_uint(bvl) : 0u;
                wbits = redux_max_u32(fb);           // md>=0 -> bits monotone
                wmaxf = __uint_as_float(wbits);

                // pre-resolve the warp's full answer: min (oid<<16|pos) among value hits
                uint32_t q = 0xFFFFFFFFu;
                #pragma unroll
                for (int j = 0; j < 16; j++)
                    q = (md[j] == wmaxf && oidpos[j] < q) ? oidpos[j] : q;
                q32w = redux_min_u32(q);             // warp min-oid packet (uniform)
            }
            if (lane == 0) {
                vbuf[p][warp] = wbits;
                pbuf[p][warp] = q32w;
            }
            __syncthreads();                          // the ONLY barrier

            // every warp redundantly reduces the 16-entry table
            uint32_t v2 = vbuf[p][lane];
            uint32_t p2 = pbuf[p][lane];
            uint32_t m2 = redux_max_u32(v2);          // block max value
            uint32_t sel = (v2 == m2) ? p2 : 0xFFFFFFFFu;
            uint32_t pm  = redux_min_u32(sel);        // min oid among ties (exact)
            int pos = (int)(pm & 0xFFFFu);

            cx = Bx[pos]; cy = By[pos]; cz = Bz[pos]; // parallel broadcast LDS
        }
        if (tid == 0) st_release_gpu(&g_prog[b], NUM_GROUP);
    } else {
        // ==================== kNN top-32 (r10 streaming, batch-major) ====================
        float* sx = s;
        float* sy = s + N;
        float* sz = s + 2 * N;

        const int kb    = blockIdx.x - B;
        const int b     = kb % B;
        const int chunk = kb / B;
        const int g     = chunk * 16 + warp;

        const float* X = xyz + (size_t)b * 3 * N;
        const float4* X4 = (const float4*)X;
        float4* sx4 = (float4*)sx;
        float4* sy4 = (float4*)sy;
        float4* sz4 = (float4*)sz;
        const int N4 = N >> 2;
        for (int n = tid; n < N4; n += TPB) {
            sx4[n] = X4[n];
            sy4[n] = X4[N4 + n];
            sz4[n] = X4[2 * N4 + n];
        }
        __syncthreads();

        if (lane == 0) {
            while (ld_acquire_gpu(&g_prog[b]) < g + 1) __nanosleep(512);
        }
        __syncwarp();

        const float* c = centers + ((size_t)b * NUM_GROUP + g) * 3;
        const float cx = __ldcg(&c[0]), cy = __ldcg(&c[1]), cz = __ldcg(&c[2]);

        // init with first 32 points, bitonic sort ascending u64 keys
        ull key;
        {
            float dx = sx[lane] - cx, dy = sy[lane] - cy, dz = sz[lane] - cz;
            float d2 = fmaf(dz, dz, fmaf(dy, dy, dx * dx));
            key = ((ull)__float_as_uint(d2) << 32) | (uint32_t)lane;
        }
        #pragma unroll
        for (int k2 = 2; k2 <= 32; k2 <<= 1) {
            #pragma unroll
            for (int j = k2 >> 1; j > 0; j >>= 1) {
                ull partner = __shfl_xor_sync(FULL, key, j);
                bool lower  = (lane & j) == 0;
                bool asc    = (lane & k2) == 0;
                ull mn = (key < partner) ? key : partner;
                ull mx = (key < partner) ? partner : key;
                key = (lower == asc) ? mn : mx;
            }
        }
        ull kmax = __shfl_sync(FULL, key, 31);

        // scalar step for points [32, 64)
        {
            int idx = 32 + lane;
            float dx = sx[idx] - cx, dy = sy[idx] - cy, dz = sz[idx] - cz;
            float d2 = fmaf(dz, dz, fmaf(dy, dy, dx * dx));
            ull nk = ((ull)__float_as_uint(d2) << 32) | (uint32_t)idx;
            unsigned mask = __ballot_sync(FULL, nk < kmax);
            while (mask) {
                int src = __ffs(mask) - 1;
                mask &= mask - 1;
                ull cand = __shfl_sync(FULL, nk, src);
                if (cand >= kmax) continue;
                int pos = __popc(__ballot_sync(FULL, key < cand));
                ull up  = __shfl_up_sync(FULL, key, 1);
                if (lane == pos)      key = cand;
                else if (lane > pos)  key = up;
                kmax = __shfl_sync(FULL, key, 31);
            }
        }

        // packed stream: 64 candidates per step
        const float2* sx2 = (const float2*)sx;
        const float2* sy2 = (const float2*)sy;
        const float2* sz2 = (const float2*)sz;
        const ull ncx = pack2(-cx, -cx), ncy = pack2(-cy, -cy), ncz = pack2(-cz, -cz);

        for (int base2 = 64; base2 < N; base2 += 64) {
            int h = (base2 >> 1) + lane;
            float2 xx = sx2[h], yy = sy2[h], zz = sz2[h];
            ull dx = addx2(pack2(xx.x, xx.y), ncx);
            ull dy = addx2(pack2(yy.x, yy.y), ncy);
            ull dz = addx2(pack2(zz.x, zz.y), ncz);
            ull m  = mulx2(dx, dx);
            m = fma2_(dy, dy, m);
            m = fma2_(dz, dz, m);
            float d0, d1; unpack2(m, d0, d1);
            int i0 = base2 + 2 * lane;
            ull k0 = ((ull)__float_as_uint(d0) << 32) | (uint32_t)i0;
            ull k1 = ((ull)__float_as_uint(d1) << 32) | (uint32_t)(i0 + 1);

            unsigned m0 = __ballot_sync(FULL, k0 < kmax);
            unsigned m1 = __ballot_sync(FULL, k1 < kmax);
            while (m0) {
                int src = __ffs(m0) - 1;
                m0 &= m0 - 1;
                ull cand = __shfl_sync(FULL, k0, src);
                if (cand >= kmax) continue;
                int pos = __popc(__ballot_sync(FULL, key < cand));
                ull up  = __shfl_up_sync(FULL, key, 1);
                if (lane == pos)      key = cand;
                else if (lane > pos)  key = up;
                kmax = __shfl_sync(FULL, key, 31);
            }
            while (m1) {
                int src = __ffs(m1) - 1;
                m1 &= m1 - 1;
                ull cand = __shfl_sync(FULL, k1, src);
                if (cand >= kmax) continue;
                int pos = __popc(__ballot_sync(FULL, key < cand));
                ull up  = __shfl_up_sync(FULL, key, 1);
                if (lane == pos)      key = cand;
                else if (lane > pos)  key = up;
                kmax = __shfl_sync(FULL, key, 31);
            }
        }

        // emit: neighborhood = point - center (lane-sorted ascending = top_k order)
        int idx = (int)(uint32_t)key;
        float ox = sx[idx] - cx, oy = sy[idx] - cy, oz = sz[idx] - cz;
        size_t o = (((size_t)b * NUM_GROUP + g) * GROUP_SIZE + lane) * 3;
        nb[o + 0] = ox;
        nb[o + 1] = oy;
        nb[o + 2] = oz;
    }
}

// ============================================================
extern "C" void kernel_launch(void* const* d_in, const int* in_sizes, int n_in,
                              void* d_out, int out_size) {
    const float* xyz = (const float*)d_in[0];
    float* out = (float*)d_out;

    const int B = out_size / (NUM_GROUP * (GROUP_SIZE + 1) * 3);
    const int N = in_sizes[0] / (3 * B);

    float* nb      = out;
    float* centers = out + (size_t)B * NUM_GROUP * GROUP_SIZE * 3;

    const int knnBlocks = B * (NUM_GROUP / 16);
    size_t smem = (size_t)(4 * N + NBKT) * sizeof(float);   // Bx,By,Bz,Bid + hist
    if (smem < 120 * 1024) smem = 120 * 1024;               // force 1 block/SM

    init_prog<<<1, MAXB>>>();

    cudaFuncSetAttribute(fused_kernel, cudaFuncAttributeMaxDynamicSharedMemorySize, (int)smem);
    fused_kernel<<<B + knnBlocks, TPB, smem>>>(xyz, nb, centers, N, B);
}